// round 8
// baseline (speedup 1.0000x reference)
#include <cuda_runtime.h>
#include <stdint.h>
#include <math.h>

// Problem constants
#define CB   4          // batch
#define CTT  4160       // total tokens = W + F
#define CF   4096       // frames
#define CWN  64         // windows (word tokens)
#define CE   256        // embed dim
#define CH   4          // heads
#define CD   64         // head dim
#define LS   15         // local window
#define HALO 7
#define QSCALE 0.125f   // 64^-0.5

// Scratch (device globals: allocation-free)
__device__ float g_qkv [CB * CTT * 768];   // (b,t, [Q|K|V] x 256)
__device__ float g_expa[CB * CF  * CE];    // (b,f,e)
__device__ float g_attn[CB * CTT * CE];    // (b,t,e) pre-output-projection

__device__ __forceinline__ unsigned int f2tf(float x) {
    unsigned int r;
    asm("cvt.rna.tf32.f32 %0, %1;" : "=r"(r) : "f"(x));
    return r;
}

__device__ __forceinline__ void mma_tf32(float* d, const unsigned int* a,
                                         const unsigned int* b) {
    asm volatile(
        "mma.sync.aligned.m16n8k8.row.col.f32.tf32.tf32.f32 "
        "{%0,%1,%2,%3}, {%4,%5,%6,%7}, {%8,%9}, {%0,%1,%2,%3};"
        : "+f"(d[0]), "+f"(d[1]), "+f"(d[2]), "+f"(d[3])
        : "r"(a[0]), "r"(a[1]), "r"(a[2]), "r"(a[3]), "r"(b[0]), "r"(b[1]));
}

// ---------------------------------------------------------------------------
// TF32 tensor-core GEMM: C[M x N] = A[M x K] @ B[K x N] + bias
// BM=128, BN=128, BK=32. Register double-buffered staging.
// ---------------------------------------------------------------------------
template <int N, int K>
__device__ __forceinline__ void tf32_gemm_core(const float* __restrict__ A,
                                               const float* __restrict__ B,
                                               const float* __restrict__ bias,
                                               float* __restrict__ C)
{
    constexpr int BM = 128, BN = 128, BK = 32;
    __shared__ unsigned int As[BK][BM + 8];   // [k][m]
    __shared__ unsigned int Bs[BN][BK + 4];   // [n][k]

    const int tid  = threadIdx.x;
    const int warp = tid >> 5, lane = tid & 31;
    const int wm_  = warp >> 2;
    const int wn_  = warp & 3;
    const int gid  = lane >> 2;
    const int tg   = lane & 3;
    const int m0   = blockIdx.y * BM;
    const int n0   = blockIdx.x * BN;

    const int a_row = tid & 127;
    const int a_kq  = (tid >> 7) * 16;
    const int b_kk  = tid & 31;
    const int b_ng  = (tid >> 5) * 16;

    float acc[4][4][4] = {};
    float4 pa[4], pb[4];

    auto load_tiles = [&](int k0) {
        const float* ap = A + (size_t)(m0 + a_row) * K + k0 + a_kq;
        const float* bp = B + (size_t)(k0 + b_kk) * N + n0 + b_ng;
        #pragma unroll
        for (int q = 0; q < 4; q++) {
            pa[q] = *(const float4*)(ap + q * 4);
            pb[q] = *(const float4*)(bp + q * 4);
        }
    };
    auto store_tiles = [&]() {
        #pragma unroll
        for (int q = 0; q < 4; q++) {
            As[a_kq + q * 4 + 0][a_row] = f2tf(pa[q].x);
            As[a_kq + q * 4 + 1][a_row] = f2tf(pa[q].y);
            As[a_kq + q * 4 + 2][a_row] = f2tf(pa[q].z);
            As[a_kq + q * 4 + 3][a_row] = f2tf(pa[q].w);
            Bs[b_ng + q * 4 + 0][b_kk] = f2tf(pb[q].x);
            Bs[b_ng + q * 4 + 1][b_kk] = f2tf(pb[q].y);
            Bs[b_ng + q * 4 + 2][b_kk] = f2tf(pb[q].z);
            Bs[b_ng + q * 4 + 3][b_kk] = f2tf(pb[q].w);
        }
    };

    load_tiles(0);
    for (int k0 = 0; k0 < K; k0 += BK) {
        store_tiles();
        __syncthreads();
        if (k0 + BK < K) load_tiles(k0 + BK);   // prefetch next tile (hidden)

        #pragma unroll
        for (int ks = 0; ks < 4; ks++) {
            const int kb = ks * 8;
            unsigned int af[4][4], bf[4][2];
            #pragma unroll
            for (int mi = 0; mi < 4; mi++) {
                int mr = wm_ * 64 + mi * 16 + gid;
                af[mi][0] = As[kb + tg    ][mr];
                af[mi][1] = As[kb + tg    ][mr + 8];
                af[mi][2] = As[kb + tg + 4][mr];
                af[mi][3] = As[kb + tg + 4][mr + 8];
            }
            #pragma unroll
            for (int ni = 0; ni < 4; ni++) {
                int nc = wn_ * 32 + ni * 8 + gid;
                bf[ni][0] = Bs[nc][kb + tg];
                bf[ni][1] = Bs[nc][kb + tg + 4];
            }
            #pragma unroll
            for (int mi = 0; mi < 4; mi++)
                #pragma unroll
                for (int ni = 0; ni < 4; ni++)
                    mma_tf32(acc[mi][ni], af[mi], bf[ni]);
        }
        __syncthreads();
    }

    #pragma unroll
    for (int ni = 0; ni < 4; ni++) {
        int c0 = n0 + wn_ * 32 + ni * 8 + tg * 2;
        float b0v = bias[c0], b1v = bias[c0 + 1];
        #pragma unroll
        for (int mi = 0; mi < 4; mi++) {
            int r0 = m0 + wm_ * 64 + mi * 16 + gid;
            float2 o0 = { acc[mi][ni][0] + b0v, acc[mi][ni][1] + b1v };
            float2 o1 = { acc[mi][ni][2] + b0v, acc[mi][ni][3] + b1v };
            *(float2*)(C + (size_t)r0 * N + c0)       = o0;
            *(float2*)(C + (size_t)(r0 + 8) * N + c0) = o1;
        }
    }
}

__global__ __launch_bounds__(256)
void k_qkv(const float* __restrict__ x, const float* __restrict__ Wq,
           const float* __restrict__ bq)
{
    tf32_gemm_core<768, 256>(x, Wq, bq, g_qkv);
}

__global__ __launch_bounds__(256)
void k_out(const float* __restrict__ Wo, const float* __restrict__ bo,
           float* __restrict__ out)
{
    tf32_gemm_core<256, 256>(g_attn, Wo, bo, out);
}

// ---------------------------------------------------------------------------
// expa[b,f,e] = sum_w wm[b,w,f] * x[b,w,e]        (K = 64 windows, fp32 exact)
// ---------------------------------------------------------------------------
__global__ __launch_bounds__(256)
void k_expa(const float* __restrict__ wm, const float* __restrict__ x)
{
    __shared__ float As[64][64];  // [w][f]
    __shared__ float Bs[64][64];  // [w][e]

    const int b  = blockIdx.z;
    const int f0 = blockIdx.y * 64;
    const int e0 = blockIdx.x * 64;
    const int tid = threadIdx.x;

    for (int i = tid; i < 64 * 16; i += 256) {
        int w  = i >> 4;
        int c4 = (i & 15) * 4;
        *(float4*)&As[w][c4] =
            *(const float4*)(wm + (size_t)(b * CWN + w) * CF + f0 + c4);
        *(float4*)&Bs[w][c4] =
            *(const float4*)(x + (size_t)(b * CTT + w) * CE + e0 + c4);
    }
    __syncthreads();

    const int tx = tid & 15, ty = tid >> 4;
    float acc[4][4] = {};
    #pragma unroll 8
    for (int w = 0; w < 64; w++) {
        float ra[4], rb[4];
        *(float4*)ra = *(const float4*)&As[w][ty * 4];
        *(float4*)rb = *(const float4*)&Bs[w][tx * 4];
        #pragma unroll
        for (int i = 0; i < 4; i++)
            #pragma unroll
            for (int j = 0; j < 4; j++)
                acc[i][j] = fmaf(ra[i], rb[j], acc[i][j]);
    }

    #pragma unroll
    for (int i = 0; i < 4; i++) {
        float4 o = { acc[i][0], acc[i][1], acc[i][2], acc[i][3] };
        *(float4*)(g_expa + (size_t)(b * CF + f0 + ty * 4 + i) * CE + e0 + tx * 4) = o;
    }
}

// ---------------------------------------------------------------------------
// Word-token rows pass through unchanged
// ---------------------------------------------------------------------------
__global__ void k_copy(const float* __restrict__ x)
{
    int i = blockIdx.x * 256 + threadIdx.x;
    int b = i >> 14;
    int r = i & 16383;
    g_attn[(size_t)b * CTT * CE + r] = x[(size_t)b * CTT * CE + r];
}

// ---------------------------------------------------------------------------
// Tensor-core attention. One block per (head-seq n, chunk c of 64 frames).
//   S[64x80] = Q @ K_halo^T     (tf32 mma; OOB K rows zeroed -> score 0)
//   band softmax (15 wide) in SIMT, weights written back as tf32 band matrix
//   O[64x64] = W_band @ V_halo  (tf32 mma)  + w0 * expa  (word-token path)
// Dynamic smem layout (uint words):
//   Qs[64][68] | Ks[80][68] | Vt[64][84] | Sw[64][84] | s0[64] | w0[64]
// ---------------------------------------------------------------------------
#define QS_STR 68
#define KS_STR 68
#define VT_STR 84
#define SW_STR 84
#define OFF_QS 0
#define OFF_KS (OFF_QS + 64 * QS_STR)
#define OFF_VT (OFF_KS + 80 * KS_STR)
#define OFF_SW (OFF_VT + 64 * VT_STR)
#define OFF_S0 (OFF_SW + 64 * SW_STR)
#define OFF_W0 (OFF_S0 + 64)
#define ATTN_SMEM_WORDS (OFF_W0 + 64)

__global__ __launch_bounds__(256)
void k_attn()
{
    extern __shared__ unsigned int sm[];
    unsigned int* Qs = sm + OFF_QS;
    unsigned int* Ks = sm + OFF_KS;
    unsigned int* Vt = sm + OFF_VT;
    unsigned int* Sw = sm + OFF_SW;   // S scores (f32 bits) then W weights (tf32)
    float* s0 = (float*)(sm + OFF_S0);
    float* w0 = (float*)(sm + OFF_W0);

    const int n = blockIdx.y, c = blockIdx.x;
    const int b = n >> 2, h = n & 3;
    const int tid  = threadIdx.x;
    const int warp = tid >> 5, lane = tid & 31;
    const int gid  = lane >> 2, tg = lane & 3;
    const int mt   = warp >> 1;   // 0..3: m-tile (16 rows)
    const int nh   = warp & 1;    // 0..1: n-half

    // ---- Stage Q (scaled, tf32) ----
    for (int i = tid; i < 64 * 16; i += 256) {
        int row = i >> 4, c4 = (i & 15) * 4;
        const float* p = g_qkv + (size_t)(b * CTT + CWN + c * 64 + row) * 768 + h * 64 + c4;
        float4 v = *(const float4*)p;
        unsigned int* q = Qs + row * QS_STR + c4;
        q[0] = f2tf(v.x * QSCALE); q[1] = f2tf(v.y * QSCALE);
        q[2] = f2tf(v.z * QSCALE); q[3] = f2tf(v.w * QSCALE);
    }
    // ---- Stage K halo (80 rows, OOB zero) and V halo transposed ----
    for (int i = tid; i < 80 * 16; i += 256) {
        int row = i >> 4, c4 = (i & 15) * 4;
        int gf = c * 64 - HALO + row;
        float4 kv = {0.f,0.f,0.f,0.f}, vv = {0.f,0.f,0.f,0.f};
        if (row < 78 && gf >= 0 && gf < CF) {
            const float* p = g_qkv + (size_t)(b * CTT + CWN + gf) * 768 + h * 64 + c4;
            kv = *(const float4*)(p + 256);
            vv = *(const float4*)(p + 512);
        }
        unsigned int* k = Ks + row * KS_STR + c4;
        k[0] = f2tf(kv.x); k[1] = f2tf(kv.y); k[2] = f2tf(kv.z); k[3] = f2tf(kv.w);
        Vt[(c4 + 0) * VT_STR + row] = f2tf(vv.x);
        Vt[(c4 + 1) * VT_STR + row] = f2tf(vv.y);
        Vt[(c4 + 2) * VT_STR + row] = f2tf(vv.z);
        Vt[(c4 + 3) * VT_STR + row] = f2tf(vv.w);
    }
    __syncthreads();

    // ---- S = Q @ K^T : [64 x 80], k=64. Warp: m-tile mt, n-cols nh*40..+39 ----
    {
        float acc[5][4] = {};
        #pragma unroll
        for (int ks = 0; ks < 8; ks++) {
            const int kb = ks * 8;
            unsigned int af[4], bf[5][2];
            int mr = mt * 16 + gid;
            af[0] = Qs[ mr      * QS_STR + kb + tg    ];
            af[1] = Qs[(mr + 8) * QS_STR + kb + tg    ];
            af[2] = Qs[ mr      * QS_STR + kb + tg + 4];
            af[3] = Qs[(mr + 8) * QS_STR + kb + tg + 4];
            #pragma unroll
            for (int ni = 0; ni < 5; ni++) {
                int nc = nh * 40 + ni * 8 + gid;
                bf[ni][0] = Ks[nc * KS_STR + kb + tg];
                bf[ni][1] = Ks[nc * KS_STR + kb + tg + 4];
            }
            #pragma unroll
            for (int ni = 0; ni < 5; ni++)
                mma_tf32(acc[ni], af, bf[ni]);
        }
        #pragma unroll
        for (int ni = 0; ni < 5; ni++) {
            int c0 = nh * 40 + ni * 8 + tg * 2;
            int r0 = mt * 16 + gid;
            Sw[ r0      * SW_STR + c0    ] = __float_as_uint(acc[ni][0]);
            Sw[ r0      * SW_STR + c0 + 1] = __float_as_uint(acc[ni][1]);
            Sw[(r0 + 8) * SW_STR + c0    ] = __float_as_uint(acc[ni][2]);
            Sw[(r0 + 8) * SW_STR + c0 + 1] = __float_as_uint(acc[ni][3]);
        }
    }
    __syncthreads();

    // ---- band softmax + word-token score (threads 0..63, one frame each) ----
    float wloc[LS];
    if (tid < 64) {
        const int f = tid;
        // local 15-softmax over band S[f][f..f+14]
        float p[LS];
        #pragma unroll
        for (int j = 0; j < LS; j++)
            p[j] = __uint_as_float(Sw[f * SW_STR + f + j]);
        float mx = p[0];
        #pragma unroll
        for (int j = 1; j < LS; j++) mx = fmaxf(mx, p[j]);
        float s = 0.f;
        #pragma unroll
        for (int j = 0; j < LS; j++) { wloc[j] = expf(p[j] - mx); s += wloc[j]; }
        const float inv = 1.f / s;
        #pragma unroll
        for (int j = 0; j < LS; j++) wloc[j] *= inv;

        // word-token score: (Q_scaled) . expa   (fp32)
        const float* ep = g_expa + (size_t)(b * CF + c * 64 + f) * CE + h * 64;
        float d = 0.f;
        #pragma unroll 16
        for (int e = 0; e < 64; e++)
            d = fmaf(__uint_as_float(Qs[f * QS_STR + e]), ep[e], d);
        s0[f] = d;
    }
    __syncthreads();

    // ---- zero W band matrix; chunk softmax over the 64 word scores ----
    for (int i = tid; i < 64 * SW_STR; i += 256) Sw[i] = 0u;
    if (tid < 64) {
        float v0 = s0[lane], v1 = s0[lane + 32];
        float M = fmaxf(v0, v1);
        #pragma unroll
        for (int off = 16; off; off >>= 1)
            M = fmaxf(M, __shfl_xor_sync(0xffffffffu, M, off));
        float S = expf(v0 - M) + expf(v1 - M);
        #pragma unroll
        for (int off = 16; off; off >>= 1)
            S += __shfl_xor_sync(0xffffffffu, S, off);
        w0[tid] = expf(s0[tid] - M) / S;
    }
    __syncthreads();

    if (tid < 64) {
        #pragma unroll
        for (int j = 0; j < LS; j++)
            Sw[tid * SW_STR + tid + j] = f2tf(wloc[j]);
    }
    __syncthreads();

    // ---- O = W @ V : [64 x 64], k=80. Warp: m-tile mt, n-cols nh*32..+31 ----
    {
        float acc[4][4] = {};
        #pragma unroll
        for (int ks = 0; ks < 10; ks++) {
            const int kb = ks * 8;
            unsigned int af[4], bf[4][2];
            int mr = mt * 16 + gid;
            af[0] = Sw[ mr      * SW_STR + kb + tg    ];
            af[1] = Sw[(mr + 8) * SW_STR + kb + tg    ];
            af[2] = Sw[ mr      * SW_STR + kb + tg + 4];
            af[3] = Sw[(mr + 8) * SW_STR + kb + tg + 4];
            #pragma unroll
            for (int ni = 0; ni < 4; ni++) {
                int nc = nh * 32 + ni * 8 + gid;
                bf[ni][0] = Vt[nc * VT_STR + kb + tg];
                bf[ni][1] = Vt[nc * VT_STR + kb + tg + 4];
            }
            #pragma unroll
            for (int ni = 0; ni < 4; ni++)
                mma_tf32(acc[ni], af, bf[ni]);
        }
        // epilogue: + w0 * expa, store to g_attn
        #pragma unroll
        for (int ni = 0; ni < 4; ni++) {
            int d0 = nh * 32 + ni * 8 + tg * 2;
            int f0 = mt * 16 + gid;
            int f1 = f0 + 8;
            float w0a = w0[f0], w0b = w0[f1];
            const float2 e0 = *(const float2*)(g_expa + (size_t)(b * CF + c * 64 + f0) * CE + h * 64 + d0);
            const float2 e1 = *(const float2*)(g_expa + (size_t)(b * CF + c * 64 + f1) * CE + h * 64 + d0);
            float2 o0 = { acc[ni][0] + w0a * e0.x, acc[ni][1] + w0a * e0.y };
            float2 o1 = { acc[ni][2] + w0b * e1.x, acc[ni][3] + w0b * e1.y };
            *(float2*)(g_attn + (size_t)(b * CTT + CWN + c * 64 + f0) * CE + h * 64 + d0) = o0;
            *(float2*)(g_attn + (size_t)(b * CTT + CWN + c * 64 + f1) * CE + h * 64 + d0) = o1;
        }
    }
}

// ---------------------------------------------------------------------------
extern "C" void kernel_launch(void* const* d_in, const int* in_sizes, int n_in,
                              void* d_out, int out_size)
{
    const float *x = nullptr, *wm = nullptr, *Wq = nullptr, *bq = nullptr,
                *Wo = nullptr, *bo = nullptr;
    for (int i = 0; i < n_in; i++) {
        switch (in_sizes[i]) {
            case 4259840: x  = (const float*)d_in[i]; break;  // (4,4160,256)
            case 1048576: wm = (const float*)d_in[i]; break;  // (4,64,4096)
            case  196608: Wq = (const float*)d_in[i]; break;  // (256,768)
            case     768: bq = (const float*)d_in[i]; break;
            case   65536: Wo = (const float*)d_in[i]; break;  // (256,256)
            case     256: bo = (const float*)d_in[i]; break;
            default: break;
        }
    }

    static bool attn_cfg = false;
    if (!attn_cfg) {
        cudaFuncSetAttribute(k_attn, cudaFuncAttributeMaxDynamicSharedMemorySize,
                             ATTN_SMEM_WORDS * 4);
        attn_cfg = true;
    }

    // 1) qkv = x @ W_qkv + b_qkv   (tf32 tensor cores, double-buffered)
    k_qkv<<<dim3(768 / 128, (CB * CTT) / 128), 256>>>(x, Wq, bq);
    // 2) expa = wm^T @ x_words
    k_expa<<<dim3(CE / 64, CF / 64, CB), 256>>>(wm, x);
    // 3) word-token passthrough rows
    k_copy<<<256, 256>>>(x);
    // 4) tensor-core local + word-token attention
    k_attn<<<dim3(CF / 64, CB * CH), 256, ATTN_SMEM_WORDS * 4>>>();
    // 5) out = attn @ W_out + b_out (tf32 tensor cores, double-buffered)
    k_out<<<dim3(256 / 128, (CB * CTT) / 128), 256>>>(Wo, bo, (float*)d_out);
}

// round 9
// speedup vs baseline: 1.2933x; 1.2933x over previous
#include <cuda_runtime.h>
#include <stdint.h>
#include <math.h>

// Problem constants
#define CB   4          // batch
#define CTT  4160       // total tokens = W + F
#define CF   4096       // frames
#define CWN  64         // windows (word tokens)
#define CE   256        // embed dim
#define CH   4          // heads
#define CD   64         // head dim
#define LS   15         // local window
#define HALO 7
#define QSCALE 0.125f   // 64^-0.5

// Scratch (device globals: allocation-free)
__device__ float g_qkv [CB * CTT * 768];   // (b,t, [Q|K|V] x 256)
__device__ float g_expa[CB * CF  * CE];    // (b,f,e)
__device__ float g_attn[CB * CTT * CE];    // (b,t,e) pre-output-projection

__device__ __forceinline__ unsigned int f2tf(float x) {
    unsigned int r;
    asm("cvt.rna.tf32.f32 %0, %1;" : "=r"(r) : "f"(x));
    return r;
}

__device__ __forceinline__ void mma_tf32(float* d, const unsigned int* a,
                                         const unsigned int* b) {
    asm volatile(
        "mma.sync.aligned.m16n8k8.row.col.f32.tf32.tf32.f32 "
        "{%0,%1,%2,%3}, {%4,%5,%6,%7}, {%8,%9}, {%0,%1,%2,%3};"
        : "+f"(d[0]), "+f"(d[1]), "+f"(d[2]), "+f"(d[3])
        : "r"(a[0]), "r"(a[1]), "r"(a[2]), "r"(a[3]), "r"(b[0]), "r"(b[1]));
}

__device__ __forceinline__ void cp16(void* smem, const void* gmem) {
    unsigned int saddr = (unsigned int)__cvta_generic_to_shared(smem);
    asm volatile("cp.async.cg.shared.global [%0], [%1], 16;"
                 :: "r"(saddr), "l"(gmem));
}
#define CP_COMMIT() asm volatile("cp.async.commit_group;" ::: "memory")
#define CP_WAIT(n)  asm volatile("cp.async.wait_group %0;" :: "n"(n) : "memory")

// ---------------------------------------------------------------------------
// TF32 tensor-core GEMM with 3-stage cp.async pipeline.
// C[M x N] = A[M x K] @ B[K x N] + bias.  BM=128, BN=128, BK=32, 256 thr.
// Smem holds fp32; tf32 conversion (cvt.rna) at fragment-load time.
// A stage: [128][36] fp32 (stride pads banks); B stage: [32][136].
// ---------------------------------------------------------------------------
#define AS_STAGE (128 * 36)
#define BS_STAGE (32 * 136)
#define GEMM_SMEM_BYTES ((3 * AS_STAGE + 3 * BS_STAGE) * 4)

template <int N, int K>
__device__ __forceinline__ void tf32_gemm_core(const float* __restrict__ A,
                                               const float* __restrict__ B,
                                               const float* __restrict__ bias,
                                               float* __restrict__ C)
{
    constexpr int BK = 32;
    constexpr int ITERS = K / BK;

    extern __shared__ float gsm[];
    float* Asm = gsm;                 // [3][128][36]
    float* Bsm = gsm + 3 * AS_STAGE;  // [3][32][136]

    const int tid  = threadIdx.x;
    const int warp = tid >> 5, lane = tid & 31;
    const int wm_  = warp >> 2;
    const int wn_  = warp & 3;
    const int gid  = lane >> 2;
    const int tg   = lane & 3;
    const int m0   = blockIdx.y * 128;
    const int n0   = blockIdx.x * 128;

    auto issue_stage = [&](int s, int k0) {
        float* as = Asm + s * AS_STAGE;
        float* bs = Bsm + s * BS_STAGE;
        #pragma unroll
        for (int p = 0; p < 4; p++) {
            int id  = tid + p * 256;
            int row = id >> 3;           // 0..127
            int kc  = (id & 7) * 4;      // 0..28
            cp16(&as[row * 36 + kc], A + (size_t)(m0 + row) * K + k0 + kc);
        }
        #pragma unroll
        for (int p = 0; p < 4; p++) {
            int id   = tid + p * 256;
            int krow = id >> 5;          // 0..31
            int nc   = (id & 31) * 4;    // 0..124
            cp16(&bs[krow * 136 + nc], B + (size_t)(k0 + krow) * N + n0 + nc);
        }
        CP_COMMIT();
    };

    float acc[4][4][4] = {};

    issue_stage(0, 0);
    issue_stage(1, BK);

    for (int it = 0; it < ITERS; it++) {
        if (it + 2 < ITERS) { CP_WAIT(1); } else { CP_WAIT(0); }
        __syncthreads();

        const int s = it % 3;
        const float* as = Asm + s * AS_STAGE;
        const float* bs = Bsm + s * BS_STAGE;

        #pragma unroll
        for (int ks = 0; ks < 4; ks++) {
            const int kb = ks * 8;
            unsigned int af[4][4], bf[4][2];
            #pragma unroll
            for (int mi = 0; mi < 4; mi++) {
                int mr = wm_ * 64 + mi * 16 + gid;
                af[mi][0] = f2tf(as[ mr      * 36 + kb + tg    ]);
                af[mi][1] = f2tf(as[(mr + 8) * 36 + kb + tg    ]);
                af[mi][2] = f2tf(as[ mr      * 36 + kb + tg + 4]);
                af[mi][3] = f2tf(as[(mr + 8) * 36 + kb + tg + 4]);
            }
            #pragma unroll
            for (int ni = 0; ni < 4; ni++) {
                int nc = wn_ * 32 + ni * 8 + gid;
                bf[ni][0] = f2tf(bs[(kb + tg    ) * 136 + nc]);
                bf[ni][1] = f2tf(bs[(kb + tg + 4) * 136 + nc]);
            }
            #pragma unroll
            for (int mi = 0; mi < 4; mi++)
                #pragma unroll
                for (int ni = 0; ni < 4; ni++)
                    mma_tf32(acc[mi][ni], af[mi], bf[ni]);
        }
        __syncthreads();

        if (it + 2 < ITERS) issue_stage((it + 2) % 3, (it + 2) * BK);
    }

    #pragma unroll
    for (int ni = 0; ni < 4; ni++) {
        int c0 = n0 + wn_ * 32 + ni * 8 + tg * 2;
        float b0v = bias[c0], b1v = bias[c0 + 1];
        #pragma unroll
        for (int mi = 0; mi < 4; mi++) {
            int r0 = m0 + wm_ * 64 + mi * 16 + gid;
            float2 o0 = { acc[mi][ni][0] + b0v, acc[mi][ni][1] + b1v };
            float2 o1 = { acc[mi][ni][2] + b0v, acc[mi][ni][3] + b1v };
            *(float2*)(C + (size_t)r0 * N + c0)       = o0;
            *(float2*)(C + (size_t)(r0 + 8) * N + c0) = o1;
        }
    }
}

__global__ __launch_bounds__(256)
void k_qkv(const float* __restrict__ x, const float* __restrict__ Wq,
           const float* __restrict__ bq)
{
    tf32_gemm_core<768, 256>(x, Wq, bq, g_qkv);
}

__global__ __launch_bounds__(256)
void k_out(const float* __restrict__ Wo, const float* __restrict__ bo,
           float* __restrict__ out)
{
    tf32_gemm_core<256, 256>(g_attn, Wo, bo, out);
}

// ---------------------------------------------------------------------------
// expa[b,f,e] = sum_w wm[b,w,f] * x[b,w,e]        (K = 64 windows, fp32 exact)
// ---------------------------------------------------------------------------
__global__ __launch_bounds__(256)
void k_expa(const float* __restrict__ wm, const float* __restrict__ x)
{
    __shared__ float As[64][64];  // [w][f]
    __shared__ float Bs[64][64];  // [w][e]

    const int b  = blockIdx.z;
    const int f0 = blockIdx.y * 64;
    const int e0 = blockIdx.x * 64;
    const int tid = threadIdx.x;

    for (int i = tid; i < 64 * 16; i += 256) {
        int w  = i >> 4;
        int c4 = (i & 15) * 4;
        *(float4*)&As[w][c4] =
            *(const float4*)(wm + (size_t)(b * CWN + w) * CF + f0 + c4);
        *(float4*)&Bs[w][c4] =
            *(const float4*)(x + (size_t)(b * CTT + w) * CE + e0 + c4);
    }
    __syncthreads();

    const int tx = tid & 15, ty = tid >> 4;
    float acc[4][4] = {};
    #pragma unroll 8
    for (int w = 0; w < 64; w++) {
        float ra[4], rb[4];
        *(float4*)ra = *(const float4*)&As[w][ty * 4];
        *(float4*)rb = *(const float4*)&Bs[w][tx * 4];
        #pragma unroll
        for (int i = 0; i < 4; i++)
            #pragma unroll
            for (int j = 0; j < 4; j++)
                acc[i][j] = fmaf(ra[i], rb[j], acc[i][j]);
    }

    #pragma unroll
    for (int i = 0; i < 4; i++) {
        float4 o = { acc[i][0], acc[i][1], acc[i][2], acc[i][3] };
        *(float4*)(g_expa + (size_t)(b * CF + f0 + ty * 4 + i) * CE + e0 + tx * 4) = o;
    }
}

// ---------------------------------------------------------------------------
// Word-token rows pass through unchanged
// ---------------------------------------------------------------------------
__global__ void k_copy(const float* __restrict__ x)
{
    int i = blockIdx.x * 256 + threadIdx.x;
    int b = i >> 14;
    int r = i & 16383;
    g_attn[(size_t)b * CTT * CE + r] = x[(size_t)b * CTT * CE + r];
}

// ---------------------------------------------------------------------------
// SIMT attention (R6 design, register-trimmed 2-pass version).
// One block per (n = b*4+h, chunk c of 64 frames). 8 warps, warp owns 8 frames.
// K/V halo zero-filled => OOB scores exactly 0 (matches reference zero-pad).
// Pass 1 computes word-token scores only (nothing held live after);
// pass 2 reloads Q/expa (L1-hot) and does local softmax + output.
// ---------------------------------------------------------------------------
__global__ __launch_bounds__(256, 3)
void k_attn()
{
    __shared__ float sK[78][64];
    __shared__ float sV[78][64];
    __shared__ float s0[64];

    const int n = blockIdx.y, c = blockIdx.x;
    const int b = n >> 2, h = n & 3;
    const int tid = threadIdx.x;

    for (int i = tid; i < 78 * 16; i += 256) {
        int row = i >> 4;
        int c4  = (i & 15) * 4;
        int gf  = c * 64 - HALO + row;
        float4 kv = {0.f, 0.f, 0.f, 0.f};
        float4 vv = {0.f, 0.f, 0.f, 0.f};
        if (gf >= 0 && gf < CF) {
            const float* p = g_qkv + (size_t)(b * CTT + CWN + gf) * 768 + h * 64 + c4;
            kv = *(const float4*)(p + 256);
            vv = *(const float4*)(p + 512);
        }
        *(float4*)&sK[row][c4] = kv;
        *(float4*)&sV[row][c4] = vv;
    }

    const int warp = tid >> 5, lane = tid & 31;

    // Pass 1: word-token scores q.expa (scaled q), one warp-reduce per frame
    #pragma unroll
    for (int fi = 0; fi < 8; fi++) {
        int lf = warp * 8 + fi;
        int f  = c * 64 + lf;
        const float* qp = g_qkv + (size_t)(b * CTT + CWN + f) * 768 + h * 64;
        const float* ep = g_expa + (size_t)(b * CF + f) * CE + h * 64;
        float p = qp[lane] * QSCALE * ep[lane]
                + qp[lane + 32] * QSCALE * ep[lane + 32];
        #pragma unroll
        for (int off = 16; off; off >>= 1)
            p += __shfl_xor_sync(0xffffffffu, p, off);
        if (lane == 0) s0[lf] = p;
    }
    __syncthreads();

    // Chunk softmax stats over 64 word scores (per warp, redundant)
    float v0 = s0[lane], v1 = s0[lane + 32];
    float M = fmaxf(v0, v1);
    #pragma unroll
    for (int off = 16; off; off >>= 1)
        M = fmaxf(M, __shfl_xor_sync(0xffffffffu, M, off));
    float S = expf(v0 - M) + expf(v1 - M);
    #pragma unroll
    for (int off = 16; off; off >>= 1)
        S += __shfl_xor_sync(0xffffffffu, S, off);
    const float Sinv = 1.f / S;

    // Pass 2: local window scores + softmax + output (reload q/expa: L1-hot)
    #pragma unroll
    for (int fi = 0; fi < 8; fi++) {
        int lf = warp * 8 + fi;
        int f  = c * 64 + lf;
        const float* qp = g_qkv + (size_t)(b * CTT + CWN + f) * 768 + h * 64;
        const float* ep = g_expa + (size_t)(b * CF + f) * CE + h * 64;
        float q0 = qp[lane] * QSCALE, q1 = qp[lane + 32] * QSCALE;
        float e0 = ep[lane],          e1 = ep[lane + 32];

        float p[LS];
        #pragma unroll
        for (int j = 0; j < LS; j++) {
            int r = lf + j;
            p[j] = q0 * sK[r][lane] + q1 * sK[r][lane + 32];
        }
        #pragma unroll
        for (int j = 0; j < LS; j++) {
            #pragma unroll
            for (int off = 16; off; off >>= 1)
                p[j] += __shfl_xor_sync(0xffffffffu, p[j], off);
        }

        float mx = p[0];
        #pragma unroll
        for (int j = 1; j < LS; j++) mx = fmaxf(mx, p[j]);
        float s = 0.f;
        #pragma unroll
        for (int j = 0; j < LS; j++) { p[j] = expf(p[j] - mx); s += p[j]; }
        const float inv = 1.f / s;

        const float w0 = expf(s0[lf] - M) * Sinv;
        float o0 = w0 * e0;
        float o1 = w0 * e1;
        #pragma unroll
        for (int j = 0; j < LS; j++) {
            int r = lf + j;
            float wj = p[j] * inv;
            o0 = fmaf(wj, sV[r][lane],      o0);
            o1 = fmaf(wj, sV[r][lane + 32], o1);
        }

        float* op = g_attn + (size_t)(b * CTT + CWN + f) * CE + h * 64;
        op[lane]      = o0;
        op[lane + 32] = o1;
    }
}

// ---------------------------------------------------------------------------
extern "C" void kernel_launch(void* const* d_in, const int* in_sizes, int n_in,
                              void* d_out, int out_size)
{
    const float *x = nullptr, *wm = nullptr, *Wq = nullptr, *bq = nullptr,
                *Wo = nullptr, *bo = nullptr;
    for (int i = 0; i < n_in; i++) {
        switch (in_sizes[i]) {
            case 4259840: x  = (const float*)d_in[i]; break;  // (4,4160,256)
            case 1048576: wm = (const float*)d_in[i]; break;  // (4,64,4096)
            case  196608: Wq = (const float*)d_in[i]; break;  // (256,768)
            case     768: bq = (const float*)d_in[i]; break;
            case   65536: Wo = (const float*)d_in[i]; break;  // (256,256)
            case     256: bo = (const float*)d_in[i]; break;
            default: break;
        }
    }

    cudaFuncSetAttribute(k_qkv, cudaFuncAttributeMaxDynamicSharedMemorySize,
                         GEMM_SMEM_BYTES);
    cudaFuncSetAttribute(k_out, cudaFuncAttributeMaxDynamicSharedMemorySize,
                         GEMM_SMEM_BYTES);

    // 1) qkv = x @ W_qkv + b_qkv   (tf32 tensor cores, cp.async 3-stage)
    k_qkv<<<dim3(768 / 128, (CB * CTT) / 128), 256, GEMM_SMEM_BYTES>>>(x, Wq, bq);
    // 2) expa = wm^T @ x_words
    k_expa<<<dim3(CE / 64, CF / 64, CB), 256>>>(wm, x);
    // 3) word-token passthrough rows
    k_copy<<<256, 256>>>(x);
    // 4) SIMT local + word-token attention (register-trimmed)
    k_attn<<<dim3(CF / 64, CB * CH), 256>>>();
    // 5) out = attn @ W_out + b_out (tf32 tensor cores, cp.async 3-stage)
    k_out<<<dim3(256 / 128, (CB * CTT) / 128), 256, GEMM_SMEM_BYTES>>>(Wo, bo, (float*)d_out);
}

// round 10
// speedup vs baseline: 1.6772x; 1.2968x over previous
#include <cuda_runtime.h>
#include <stdint.h>
#include <math.h>

// Problem constants
#define CB   4          // batch
#define CTT  4160       // total tokens = W + F
#define CF   4096       // frames
#define CWN  64         // windows (word tokens)
#define CE   256        // embed dim
#define CH   4          // heads
#define CD   64         // head dim
#define LS   15         // local window
#define HALO 7
#define QSCALE 0.125f   // 64^-0.5 (exact power of two)

// Scratch (device globals: allocation-free)
__device__ float g_qkv [CB * CTT * 768];   // (b,t, [Q|K|V] x 256)
__device__ float g_expa[CB * CF  * CE];    // (b,f,e)
__device__ float g_attn[CB * CTT * CE];    // (b,t,e) pre-output-projection

__device__ __forceinline__ unsigned int f2tf(float x) {
    unsigned int r;
    asm("cvt.rna.tf32.f32 %0, %1;" : "=r"(r) : "f"(x));
    return r;
}

__device__ __forceinline__ void mma_tf32(float* d, const unsigned int* a,
                                         const unsigned int* b) {
    asm volatile(
        "mma.sync.aligned.m16n8k8.row.col.f32.tf32.tf32.f32 "
        "{%0,%1,%2,%3}, {%4,%5,%6,%7}, {%8,%9}, {%0,%1,%2,%3};"
        : "+f"(d[0]), "+f"(d[1]), "+f"(d[2]), "+f"(d[3])
        : "r"(a[0]), "r"(a[1]), "r"(a[2]), "r"(a[3]), "r"(b[0]), "r"(b[1]));
}

__device__ __forceinline__ void cp16(void* smem, const void* gmem) {
    unsigned int saddr = (unsigned int)__cvta_generic_to_shared(smem);
    asm volatile("cp.async.cg.shared.global [%0], [%1], 16;"
                 :: "r"(saddr), "l"(gmem));
}
// cp.async with src-size: bytes beyond src_sz are zero-filled (src_sz=0 -> all zeros)
__device__ __forceinline__ void cp16z(void* smem, const void* gmem, int src_sz) {
    unsigned int saddr = (unsigned int)__cvta_generic_to_shared(smem);
    asm volatile("cp.async.cg.shared.global [%0], [%1], 16, %2;"
                 :: "r"(saddr), "l"(gmem), "r"(src_sz));
}
#define CP_COMMIT() asm volatile("cp.async.commit_group;" ::: "memory")
#define CP_WAIT(n)  asm volatile("cp.async.wait_group %0;" :: "n"(n) : "memory")

// ---------------------------------------------------------------------------
// TF32 tensor-core GEMM with 3-stage cp.async pipeline. (unchanged from R9)
// ---------------------------------------------------------------------------
#define AS_STAGE (128 * 36)
#define BS_STAGE (32 * 136)
#define GEMM_SMEM_BYTES ((3 * AS_STAGE + 3 * BS_STAGE) * 4)

template <int N, int K>
__device__ __forceinline__ void tf32_gemm_core(const float* __restrict__ A,
                                               const float* __restrict__ B,
                                               const float* __restrict__ bias,
                                               float* __restrict__ C)
{
    constexpr int BK = 32;
    constexpr int ITERS = K / BK;

    extern __shared__ float gsm[];
    float* Asm = gsm;                 // [3][128][36]
    float* Bsm = gsm + 3 * AS_STAGE;  // [3][32][136]

    const int tid  = threadIdx.x;
    const int warp = tid >> 5, lane = tid & 31;
    const int wm_  = warp >> 2;
    const int wn_  = warp & 3;
    const int gid  = lane >> 2;
    const int tg   = lane & 3;
    const int m0   = blockIdx.y * 128;
    const int n0   = blockIdx.x * 128;

    auto issue_stage = [&](int s, int k0) {
        float* as = Asm + s * AS_STAGE;
        float* bs = Bsm + s * BS_STAGE;
        #pragma unroll
        for (int p = 0; p < 4; p++) {
            int id  = tid + p * 256;
            int row = id >> 3;
            int kc  = (id & 7) * 4;
            cp16(&as[row * 36 + kc], A + (size_t)(m0 + row) * K + k0 + kc);
        }
        #pragma unroll
        for (int p = 0; p < 4; p++) {
            int id   = tid + p * 256;
            int krow = id >> 5;
            int nc   = (id & 31) * 4;
            cp16(&bs[krow * 136 + nc], B + (size_t)(k0 + krow) * N + n0 + nc);
        }
        CP_COMMIT();
    };

    float acc[4][4][4] = {};

    issue_stage(0, 0);
    issue_stage(1, BK);

    for (int it = 0; it < ITERS; it++) {
        if (it + 2 < ITERS) { CP_WAIT(1); } else { CP_WAIT(0); }
        __syncthreads();

        const int s = it % 3;
        const float* as = Asm + s * AS_STAGE;
        const float* bs = Bsm + s * BS_STAGE;

        #pragma unroll
        for (int ks = 0; ks < 4; ks++) {
            const int kb = ks * 8;
            unsigned int af[4][4], bf[4][2];
            #pragma unroll
            for (int mi = 0; mi < 4; mi++) {
                int mr = wm_ * 64 + mi * 16 + gid;
                af[mi][0] = f2tf(as[ mr      * 36 + kb + tg    ]);
                af[mi][1] = f2tf(as[(mr + 8) * 36 + kb + tg    ]);
                af[mi][2] = f2tf(as[ mr      * 36 + kb + tg + 4]);
                af[mi][3] = f2tf(as[(mr + 8) * 36 + kb + tg + 4]);
            }
            #pragma unroll
            for (int ni = 0; ni < 4; ni++) {
                int nc = wn_ * 32 + ni * 8 + gid;
                bf[ni][0] = f2tf(bs[(kb + tg    ) * 136 + nc]);
                bf[ni][1] = f2tf(bs[(kb + tg + 4) * 136 + nc]);
            }
            #pragma unroll
            for (int mi = 0; mi < 4; mi++)
                #pragma unroll
                for (int ni = 0; ni < 4; ni++)
                    mma_tf32(acc[mi][ni], af[mi], bf[ni]);
        }
        __syncthreads();

        if (it + 2 < ITERS) issue_stage((it + 2) % 3, (it + 2) * BK);
    }

    #pragma unroll
    for (int ni = 0; ni < 4; ni++) {
        int c0 = n0 + wn_ * 32 + ni * 8 + tg * 2;
        float b0v = bias[c0], b1v = bias[c0 + 1];
        #pragma unroll
        for (int mi = 0; mi < 4; mi++) {
            int r0 = m0 + wm_ * 64 + mi * 16 + gid;
            float2 o0 = { acc[mi][ni][0] + b0v, acc[mi][ni][1] + b1v };
            float2 o1 = { acc[mi][ni][2] + b0v, acc[mi][ni][3] + b1v };
            *(float2*)(C + (size_t)r0 * N + c0)       = o0;
            *(float2*)(C + (size_t)(r0 + 8) * N + c0) = o1;
        }
    }
}

__global__ __launch_bounds__(256)
void k_qkv(const float* __restrict__ x, const float* __restrict__ Wq,
           const float* __restrict__ bq)
{
    tf32_gemm_core<768, 256>(x, Wq, bq, g_qkv);
}

__global__ __launch_bounds__(256)
void k_out(const float* __restrict__ Wo, const float* __restrict__ bo,
           float* __restrict__ out)
{
    tf32_gemm_core<256, 256>(g_attn, Wo, bo, out);
}

// ---------------------------------------------------------------------------
// expa[b,f,e] = sum_w wm[b,w,f] * x[b,w,e]   (K = 64 windows, fp32 exact)
// ---------------------------------------------------------------------------
__global__ __launch_bounds__(256)
void k_expa(const float* __restrict__ wm, const float* __restrict__ x)
{
    __shared__ float As[64][64];  // [w][f]
    __shared__ float Bs[64][64];  // [w][e]

    const int b  = blockIdx.z;
    const int f0 = blockIdx.y * 64;
    const int e0 = blockIdx.x * 64;
    const int tid = threadIdx.x;

    for (int i = tid; i < 64 * 16; i += 256) {
        int w  = i >> 4;
        int c4 = (i & 15) * 4;
        *(float4*)&As[w][c4] =
            *(const float4*)(wm + (size_t)(b * CWN + w) * CF + f0 + c4);
        *(float4*)&Bs[w][c4] =
            *(const float4*)(x + (size_t)(b * CTT + w) * CE + e0 + c4);
    }
    __syncthreads();

    const int tx = tid & 15, ty = tid >> 4;
    float acc[4][4] = {};
    #pragma unroll 8
    for (int w = 0; w < 64; w++) {
        float ra[4], rb[4];
        *(float4*)ra = *(const float4*)&As[w][ty * 4];
        *(float4*)rb = *(const float4*)&Bs[w][tx * 4];
        #pragma unroll
        for (int i = 0; i < 4; i++)
            #pragma unroll
            for (int j = 0; j < 4; j++)
                acc[i][j] = fmaf(ra[i], rb[j], acc[i][j]);
    }

    #pragma unroll
    for (int i = 0; i < 4; i++) {
        float4 o = { acc[i][0], acc[i][1], acc[i][2], acc[i][3] };
        *(float4*)(g_expa + (size_t)(b * CF + f0 + ty * 4 + i) * CE + e0 + tx * 4) = o;
    }
}

// ---------------------------------------------------------------------------
// Word-token rows pass through unchanged
// ---------------------------------------------------------------------------
__global__ void k_copy(const float* __restrict__ x)
{
    int i = blockIdx.x * 256 + threadIdx.x;
    int b = i >> 14;
    int r = i & 16383;
    g_attn[(size_t)b * CTT * CE + r] = x[(size_t)b * CTT * CE + r];
}

// ---------------------------------------------------------------------------
// Attention v3: shuffle-free score phase (lane-per-score), cp.async staging.
// One block per (n = b*4+h, chunk c of 64 frames), 256 threads.
// Layout (dynamic smem, floats): sK[78][68] | sV[78][68] | sQ[64][68] |
//                                sS[64][17] | s0[64] | w0[64]
// Stride 68: float4-aligned, banks (4*row+e)%32; sS stride 17 coprime to 32.
// OOB halo rows zero-filled (cp.async src-size=0) -> scores exactly 0,
// matching the reference's zero padding. QSCALE=2^-3 applied post-sum (exact).
// ---------------------------------------------------------------------------
#define KST 68
#define AROWS 78
#define AOFF_K 0
#define AOFF_V (AROWS * KST)                 // 5304
#define AOFF_Q (2 * AROWS * KST)             // 10608
#define AOFF_S (AOFF_Q + 64 * KST)           // 14960
#define AOFF_S0 (AOFF_S + 64 * 17)           // 16048
#define AOFF_W0 (AOFF_S0 + 64)               // 16112
#define ATTN_WORDS (AOFF_W0 + 64)            // 16176 -> 64704 B

__global__ __launch_bounds__(256, 3)
void k_attn()
{
    extern __shared__ float sa[];
    float* sK = sa + AOFF_K;
    float* sV = sa + AOFF_V;
    float* sQ = sa + AOFF_Q;
    float* sS = sa + AOFF_S;
    float* s0 = sa + AOFF_S0;
    float* w0 = sa + AOFF_W0;

    const int n = blockIdx.y, c = blockIdx.x;
    const int b = n >> 2, h = n & 3;
    const int tid = threadIdx.x;
    const int warp = tid >> 5, lane = tid & 31;

    // ---- stage K/V halo (zero-filled OOB) + raw Q via cp.async ----
    for (int i = tid; i < AROWS * 16; i += 256) {
        int row = i >> 4, c4 = (i & 15) * 4;
        int gf  = c * 64 - HALO + row;
        int ok  = (gf >= 0 && gf < CF);
        int gfc = ok ? gf : 0;
        const float* base = g_qkv + (size_t)(b * CTT + CWN + gfc) * 768 + h * 64 + c4;
        cp16z(&sK[row * KST + c4], base + 256, ok ? 16 : 0);
        cp16z(&sV[row * KST + c4], base + 512, ok ? 16 : 0);
    }
    for (int i = tid; i < 64 * 16; i += 256) {
        int row = i >> 4, c4 = (i & 15) * 4;
        cp16z(&sQ[row * KST + c4],
              g_qkv + (size_t)(b * CTT + CWN + c * 64 + row) * 768 + h * 64 + c4, 16);
    }
    CP_COMMIT();
    CP_WAIT(0);
    __syncthreads();

    // ---- phase 1: word-token scores (warp reduce, cheap) ----
    #pragma unroll
    for (int fi = 0; fi < 8; fi++) {
        int lf = warp * 8 + fi;
        const float* ep = g_expa + (size_t)(b * CF + c * 64 + lf) * CE + h * 64;
        float p = sQ[lf * KST + lane] * ep[lane]
                + sQ[lf * KST + lane + 32] * ep[lane + 32];
        #pragma unroll
        for (int off = 16; off; off >>= 1)
            p += __shfl_xor_sync(0xffffffffu, p, off);
        if (lane == 0) s0[lf] = p * QSCALE;
    }

    // ---- phase A: local scores, lane-per-score, float4 LDS, no shuffles ----
    {
        const int j    = lane & 15;
        const int half = lane >> 4;
        #pragma unroll
        for (int pass = 0; pass < 4; pass++) {
            int f = pass * 16 + warp * 2 + half;
            if (j < LS) {
                const float* qr = sQ + f * KST;
                const float* kr = sK + (f + j) * KST;
                float a0 = 0.f, a1 = 0.f;
                #pragma unroll
                for (int e = 0; e < 64; e += 4) {
                    float4 qv = *(const float4*)(qr + e);
                    float4 kv = *(const float4*)(kr + e);
                    a0 = fmaf(qv.x, kv.x, a0);
                    a1 = fmaf(qv.y, kv.y, a1);
                    a0 = fmaf(qv.z, kv.z, a0);
                    a1 = fmaf(qv.w, kv.w, a1);
                }
                sS[f * 17 + j] = (a0 + a1) * QSCALE;
            }
        }
    }
    __syncthreads();

    // ---- chunk softmax stats + w0 (warp 0); local softmax (tid<64) ----
    if (warp == 0) {
        float v0 = s0[lane], v1 = s0[lane + 32];
        float M = fmaxf(v0, v1);
        #pragma unroll
        for (int off = 16; off; off >>= 1)
            M = fmaxf(M, __shfl_xor_sync(0xffffffffu, M, off));
        float S = expf(v0 - M) + expf(v1 - M);
        #pragma unroll
        for (int off = 16; off; off >>= 1)
            S += __shfl_xor_sync(0xffffffffu, S, off);
        float Sinv = 1.f / S;
        w0[lane]      = expf(v0 - M) * Sinv;
        w0[lane + 32] = expf(v1 - M) * Sinv;
    }
    if (tid < 64) {
        float p[LS];
        #pragma unroll
        for (int j = 0; j < LS; j++) p[j] = sS[tid * 17 + j];
        float mx = p[0];
        #pragma unroll
        for (int j = 1; j < LS; j++) mx = fmaxf(mx, p[j]);
        float s = 0.f;
        #pragma unroll
        for (int j = 0; j < LS; j++) { p[j] = expf(p[j] - mx); s += p[j]; }
        float inv = 1.f / s;
        #pragma unroll
        for (int j = 0; j < LS; j++) sS[tid * 17 + j] = p[j] * inv;
    }
    __syncthreads();

    // ---- output: o = w0*expa + sum_j w_j * V ----
    #pragma unroll
    for (int fi = 0; fi < 8; fi++) {
        int lf = warp * 8 + fi;
        const float* ep = g_expa + (size_t)(b * CF + c * 64 + lf) * CE + h * 64;
        float wv = w0[lf];
        float o0 = wv * ep[lane];
        float o1 = wv * ep[lane + 32];
        #pragma unroll
        for (int j = 0; j < LS; j++) {
            float wj = sS[lf * 17 + j];
            const float* vr = sV + (lf + j) * KST;
            o0 = fmaf(wj, vr[lane],      o0);
            o1 = fmaf(wj, vr[lane + 32], o1);
        }
        float* op = g_attn + (size_t)(b * CTT + CWN + c * 64 + lf) * CE + h * 64;
        op[lane]      = o0;
        op[lane + 32] = o1;
    }
}

// ---------------------------------------------------------------------------
extern "C" void kernel_launch(void* const* d_in, const int* in_sizes, int n_in,
                              void* d_out, int out_size)
{
    const float *x = nullptr, *wm = nullptr, *Wq = nullptr, *bq = nullptr,
                *Wo = nullptr, *bo = nullptr;
    for (int i = 0; i < n_in; i++) {
        switch (in_sizes[i]) {
            case 4259840: x  = (const float*)d_in[i]; break;  // (4,4160,256)
            case 1048576: wm = (const float*)d_in[i]; break;  // (4,64,4096)
            case  196608: Wq = (const float*)d_in[i]; break;  // (256,768)
            case     768: bq = (const float*)d_in[i]; break;
            case   65536: Wo = (const float*)d_in[i]; break;  // (256,256)
            case     256: bo = (const float*)d_in[i]; break;
            default: break;
        }
    }

    cudaFuncSetAttribute(k_qkv, cudaFuncAttributeMaxDynamicSharedMemorySize,
                         GEMM_SMEM_BYTES);
    cudaFuncSetAttribute(k_out, cudaFuncAttributeMaxDynamicSharedMemorySize,
                         GEMM_SMEM_BYTES);
    cudaFuncSetAttribute(k_attn, cudaFuncAttributeMaxDynamicSharedMemorySize,
                         ATTN_WORDS * 4);

    // 1) qkv = x @ W_qkv + b_qkv   (tf32 tensor cores, cp.async 3-stage)
    k_qkv<<<dim3(768 / 128, (CB * CTT) / 128), 256, GEMM_SMEM_BYTES>>>(x, Wq, bq);
    // 2) expa = wm^T @ x_words
    k_expa<<<dim3(CE / 64, CF / 64, CB), 256>>>(wm, x);
    // 3) word-token passthrough rows
    k_copy<<<256, 256>>>(x);
    // 4) shuffle-free SIMT attention
    k_attn<<<dim3(CF / 64, CB * CH), 256, ATTN_WORDS * 4>>>();
    // 5) out = attn @ W_out + b_out (tf32 tensor cores, cp.async 3-stage)
    k_out<<<dim3(256 / 128, (CB * CTT) / 128), 256, GEMM_SMEM_BYTES>>>(Wo, bo, (float*)d_out);
}

// round 11
// speedup vs baseline: 1.6826x; 1.0032x over previous
#include <cuda_runtime.h>
#include <stdint.h>
#include <math.h>

// Problem constants
#define CB   4          // batch
#define CTT  4160       // total tokens = W + F
#define CF   4096       // frames
#define CWN  64         // windows (word tokens)
#define CE   256        // embed dim
#define CH   4          // heads
#define CD   64         // head dim
#define LS   15         // local window
#define HALO 7
#define QSCALE 0.125f   // 64^-0.5 (exact power of two)

// Scratch (device globals: allocation-free)
__device__ float g_qkv [CB * CTT * 768];   // (b,t, [Q|K|V] x 256)
__device__ float g_expa[CB * CF  * CE];    // (b,f,e)
__device__ float g_attn[CB * CTT * CE];    // (b,t,e) pre-output-projection

__device__ __forceinline__ unsigned int f2tf(float x) {
    unsigned int r;
    asm("cvt.rna.tf32.f32 %0, %1;" : "=r"(r) : "f"(x));
    return r;
}

__device__ __forceinline__ void mma_tf32(float* d, const unsigned int* a,
                                         const unsigned int* b) {
    asm volatile(
        "mma.sync.aligned.m16n8k8.row.col.f32.tf32.tf32.f32 "
        "{%0,%1,%2,%3}, {%4,%5,%6,%7}, {%8,%9}, {%0,%1,%2,%3};"
        : "+f"(d[0]), "+f"(d[1]), "+f"(d[2]), "+f"(d[3])
        : "r"(a[0]), "r"(a[1]), "r"(a[2]), "r"(a[3]), "r"(b[0]), "r"(b[1]));
}

__device__ __forceinline__ void cp16(void* smem, const void* gmem) {
    unsigned int saddr = (unsigned int)__cvta_generic_to_shared(smem);
    asm volatile("cp.async.cg.shared.global [%0], [%1], 16;"
                 :: "r"(saddr), "l"(gmem));
}
// cp.async with src-size: bytes beyond src_sz are zero-filled (src_sz=0 -> all zeros)
__device__ __forceinline__ void cp16z(void* smem, const void* gmem, int src_sz) {
    unsigned int saddr = (unsigned int)__cvta_generic_to_shared(smem);
    asm volatile("cp.async.cg.shared.global [%0], [%1], 16, %2;"
                 :: "r"(saddr), "l"(gmem), "r"(src_sz));
}
#define CP_COMMIT() asm volatile("cp.async.commit_group;" ::: "memory")
#define CP_WAIT(n)  asm volatile("cp.async.wait_group %0;" :: "n"(n) : "memory")

// ---------------------------------------------------------------------------
// TF32 tensor-core GEMM with 3-stage cp.async pipeline. (unchanged from R9)
// ---------------------------------------------------------------------------
#define AS_STAGE (128 * 36)
#define BS_STAGE (32 * 136)
#define GEMM_SMEM_BYTES ((3 * AS_STAGE + 3 * BS_STAGE) * 4)

template <int N, int K>
__device__ __forceinline__ void tf32_gemm_core(const float* __restrict__ A,
                                               const float* __restrict__ B,
                                               const float* __restrict__ bias,
                                               float* __restrict__ C)
{
    constexpr int BK = 32;
    constexpr int ITERS = K / BK;

    extern __shared__ float gsm[];
    float* Asm = gsm;                 // [3][128][36]
    float* Bsm = gsm + 3 * AS_STAGE;  // [3][32][136]

    const int tid  = threadIdx.x;
    const int warp = tid >> 5, lane = tid & 31;
    const int wm_  = warp >> 2;
    const int wn_  = warp & 3;
    const int gid  = lane >> 2;
    const int tg   = lane & 3;
    const int m0   = blockIdx.y * 128;
    const int n0   = blockIdx.x * 128;

    auto issue_stage = [&](int s, int k0) {
        float* as = Asm + s * AS_STAGE;
        float* bs = Bsm + s * BS_STAGE;
        #pragma unroll
        for (int p = 0; p < 4; p++) {
            int id  = tid + p * 256;
            int row = id >> 3;
            int kc  = (id & 7) * 4;
            cp16(&as[row * 36 + kc], A + (size_t)(m0 + row) * K + k0 + kc);
        }
        #pragma unroll
        for (int p = 0; p < 4; p++) {
            int id   = tid + p * 256;
            int krow = id >> 5;
            int nc   = (id & 31) * 4;
            cp16(&bs[krow * 136 + nc], B + (size_t)(k0 + krow) * N + n0 + nc);
        }
        CP_COMMIT();
    };

    float acc[4][4][4] = {};

    issue_stage(0, 0);
    issue_stage(1, BK);

    for (int it = 0; it < ITERS; it++) {
        if (it + 2 < ITERS) { CP_WAIT(1); } else { CP_WAIT(0); }
        __syncthreads();

        const int s = it % 3;
        const float* as = Asm + s * AS_STAGE;
        const float* bs = Bsm + s * BS_STAGE;

        #pragma unroll
        for (int ks = 0; ks < 4; ks++) {
            const int kb = ks * 8;
            unsigned int af[4][4], bf[4][2];
            #pragma unroll
            for (int mi = 0; mi < 4; mi++) {
                int mr = wm_ * 64 + mi * 16 + gid;
                af[mi][0] = f2tf(as[ mr      * 36 + kb + tg    ]);
                af[mi][1] = f2tf(as[(mr + 8) * 36 + kb + tg    ]);
                af[mi][2] = f2tf(as[ mr      * 36 + kb + tg + 4]);
                af[mi][3] = f2tf(as[(mr + 8) * 36 + kb + tg + 4]);
            }
            #pragma unroll
            for (int ni = 0; ni < 4; ni++) {
                int nc = wn_ * 32 + ni * 8 + gid;
                bf[ni][0] = f2tf(bs[(kb + tg    ) * 136 + nc]);
                bf[ni][1] = f2tf(bs[(kb + tg + 4) * 136 + nc]);
            }
            #pragma unroll
            for (int mi = 0; mi < 4; mi++)
                #pragma unroll
                for (int ni = 0; ni < 4; ni++)
                    mma_tf32(acc[mi][ni], af[mi], bf[ni]);
        }
        __syncthreads();

        if (it + 2 < ITERS) issue_stage((it + 2) % 3, (it + 2) * BK);
    }

    #pragma unroll
    for (int ni = 0; ni < 4; ni++) {
        int c0 = n0 + wn_ * 32 + ni * 8 + tg * 2;
        float b0v = bias[c0], b1v = bias[c0 + 1];
        #pragma unroll
        for (int mi = 0; mi < 4; mi++) {
            int r0 = m0 + wm_ * 64 + mi * 16 + gid;
            float2 o0 = { acc[mi][ni][0] + b0v, acc[mi][ni][1] + b1v };
            float2 o1 = { acc[mi][ni][2] + b0v, acc[mi][ni][3] + b1v };
            *(float2*)(C + (size_t)r0 * N + c0)       = o0;
            *(float2*)(C + (size_t)(r0 + 8) * N + c0) = o1;
        }
    }
}

__global__ __launch_bounds__(256)
void k_qkv(const float* __restrict__ x, const float* __restrict__ Wq,
           const float* __restrict__ bq)
{
    tf32_gemm_core<768, 256>(x, Wq, bq, g_qkv);
}

__global__ __launch_bounds__(256)
void k_out(const float* __restrict__ Wo, const float* __restrict__ bo,
           float* __restrict__ out)
{
    tf32_gemm_core<256, 256>(g_attn, Wo, bo, out);
}

// ---------------------------------------------------------------------------
// expa[b,f,e] = sum_w wm[b,w,f] * x[b,w,e]   (K = 64 windows, fp32 exact)
// gridDim.z == 5: the z==4 slice does the word-token passthrough copy.
// ---------------------------------------------------------------------------
__global__ __launch_bounds__(256)
void k_expa(const float* __restrict__ wm, const float* __restrict__ x)
{
    if (blockIdx.z == 4) {
        // word-token rows pass through: g_attn[b, t<64, :] = x[b, t<64, :]
        int i = ((blockIdx.y * 4 + blockIdx.x) * 256) + threadIdx.x; // 0..65535
        int b = i >> 14;
        int r = i & 16383;
        g_attn[(size_t)b * CTT * CE + r] = x[(size_t)b * CTT * CE + r];
        return;
    }

    __shared__ float As[64][64];  // [w][f]
    __shared__ float Bs[64][64];  // [w][e]

    const int b  = blockIdx.z;
    const int f0 = blockIdx.y * 64;
    const int e0 = blockIdx.x * 64;
    const int tid = threadIdx.x;

    for (int i = tid; i < 64 * 16; i += 256) {
        int w  = i >> 4;
        int c4 = (i & 15) * 4;
        *(float4*)&As[w][c4] =
            *(const float4*)(wm + (size_t)(b * CWN + w) * CF + f0 + c4);
        *(float4*)&Bs[w][c4] =
            *(const float4*)(x + (size_t)(b * CTT + w) * CE + e0 + c4);
    }
    __syncthreads();

    const int tx = tid & 15, ty = tid >> 4;
    float acc[4][4] = {};
    #pragma unroll 8
    for (int w = 0; w < 64; w++) {
        float ra[4], rb[4];
        *(float4*)ra = *(const float4*)&As[w][ty * 4];
        *(float4*)rb = *(const float4*)&Bs[w][tx * 4];
        #pragma unroll
        for (int i = 0; i < 4; i++)
            #pragma unroll
            for (int j = 0; j < 4; j++)
                acc[i][j] = fmaf(ra[i], rb[j], acc[i][j]);
    }

    #pragma unroll
    for (int i = 0; i < 4; i++) {
        float4 o = { acc[i][0], acc[i][1], acc[i][2], acc[i][3] };
        *(float4*)(g_expa + (size_t)(b * CF + f0 + ty * 4 + i) * CE + e0 + tx * 4) = o;
    }
}

// ---------------------------------------------------------------------------
// Attention v4: shuffle-free scores, NO Q in smem (read via gmem broadcast),
// 46.2 KB smem + <=64 regs -> 4 blocks/SM for doubled MLP.
// One block per (n = b*4+h, chunk c of 64 frames), 256 threads.
// smem (floats): sK[78][68] | sV[78][68] | sS[64][17] | s0[64] | w0[64]
// OOB halo rows zero-filled (cp.async src-size=0) -> scores exactly 0,
// matching the reference's zero padding. QSCALE=2^-3 post-sum (exact).
// ---------------------------------------------------------------------------
#define KST 68
#define AROWS 78
#define AOFF_K 0
#define AOFF_V (AROWS * KST)                 // 5304
#define AOFF_S (2 * AROWS * KST)             // 10608
#define AOFF_S0 (AOFF_S + 64 * 17)           // 11696
#define AOFF_W0 (AOFF_S0 + 64)               // 11760
#define ATTN_WORDS (AOFF_W0 + 64)            // 11824 -> 47296 B

__global__ __launch_bounds__(256, 4)
void k_attn()
{
    extern __shared__ float sa[];
    float* sK = sa + AOFF_K;
    float* sV = sa + AOFF_V;
    float* sS = sa + AOFF_S;
    float* s0 = sa + AOFF_S0;
    float* w0 = sa + AOFF_W0;

    const int n = blockIdx.y, c = blockIdx.x;
    const int b = n >> 2, h = n & 3;
    const int tid = threadIdx.x;
    const int warp = tid >> 5, lane = tid & 31;

    const float* Qg = g_qkv + (size_t)(b * CTT + CWN + c * 64) * 768 + h * 64;

    // ---- stage K/V halo (zero-filled OOB) via cp.async ----
    for (int i = tid; i < AROWS * 16; i += 256) {
        int row = i >> 4, c4 = (i & 15) * 4;
        int gf  = c * 64 - HALO + row;
        int ok  = (gf >= 0 && gf < CF);
        int gfc = ok ? gf : 0;
        const float* base = g_qkv + (size_t)(b * CTT + CWN + gfc) * 768 + h * 64 + c4;
        cp16z(&sK[row * KST + c4], base + 256, ok ? 16 : 0);
        cp16z(&sV[row * KST + c4], base + 512, ok ? 16 : 0);
    }
    CP_COMMIT();

    // ---- word-token scores from gmem Q (overlaps with K/V arrival) ----
    #pragma unroll
    for (int fi = 0; fi < 8; fi++) {
        int lf = warp * 8 + fi;
        const float* qp = Qg + (size_t)lf * 768;
        const float* ep = g_expa + (size_t)(b * CF + c * 64 + lf) * CE + h * 64;
        float p = qp[lane] * ep[lane] + qp[lane + 32] * ep[lane + 32];
        #pragma unroll
        for (int off = 16; off; off >>= 1)
            p += __shfl_xor_sync(0xffffffffu, p, off);
        if (lane == 0) s0[lf] = p * QSCALE;
    }

    CP_WAIT(0);
    __syncthreads();

    // ---- local scores: lane-per-score, Q broadcast from gmem, K from smem ----
    {
        const int j    = lane & 15;
        const int half = lane >> 4;
        #pragma unroll
        for (int pass = 0; pass < 4; pass++) {
            int f = pass * 16 + warp * 2 + half;
            if (j < LS) {
                const float* qr = Qg + (size_t)f * 768;
                const float* kr = sK + (f + j) * KST;
                float a0 = 0.f, a1 = 0.f;
                #pragma unroll
                for (int e = 0; e < 64; e += 4) {
                    float4 qv = *(const float4*)(qr + e);
                    float4 kv = *(const float4*)(kr + e);
                    a0 = fmaf(qv.x, kv.x, a0);
                    a1 = fmaf(qv.y, kv.y, a1);
                    a0 = fmaf(qv.z, kv.z, a0);
                    a1 = fmaf(qv.w, kv.w, a1);
                }
                sS[f * 17 + j] = (a0 + a1) * QSCALE;
            }
        }
    }
    __syncthreads();

    // ---- chunk softmax (warp 0) + local softmax (tid<64) ----
    if (warp == 0) {
        float v0 = s0[lane], v1 = s0[lane + 32];
        float M = fmaxf(v0, v1);
        #pragma unroll
        for (int off = 16; off; off >>= 1)
            M = fmaxf(M, __shfl_xor_sync(0xffffffffu, M, off));
        float S = expf(v0 - M) + expf(v1 - M);
        #pragma unroll
        for (int off = 16; off; off >>= 1)
            S += __shfl_xor_sync(0xffffffffu, S, off);
        float Sinv = 1.f / S;
        w0[lane]      = expf(v0 - M) * Sinv;
        w0[lane + 32] = expf(v1 - M) * Sinv;
    }
    if (tid < 64) {
        float p[LS];
        #pragma unroll
        for (int j = 0; j < LS; j++) p[j] = sS[tid * 17 + j];
        float mx = p[0];
        #pragma unroll
        for (int j = 1; j < LS; j++) mx = fmaxf(mx, p[j]);
        float s = 0.f;
        #pragma unroll
        for (int j = 0; j < LS; j++) { p[j] = expf(p[j] - mx); s += p[j]; }
        float inv = 1.f / s;
        #pragma unroll
        for (int j = 0; j < LS; j++) sS[tid * 17 + j] = p[j] * inv;
    }
    __syncthreads();

    // ---- output: o = w0*expa + sum_j w_j * V ----
    #pragma unroll
    for (int fi = 0; fi < 8; fi++) {
        int lf = warp * 8 + fi;
        const float* ep = g_expa + (size_t)(b * CF + c * 64 + lf) * CE + h * 64;
        float wv = w0[lf];
        float o0 = wv * ep[lane];
        float o1 = wv * ep[lane + 32];
        #pragma unroll
        for (int j = 0; j < LS; j++) {
            float wj = sS[lf * 17 + j];
            const float* vr = sV + (lf + j) * KST;
            o0 = fmaf(wj, vr[lane],      o0);
            o1 = fmaf(wj, vr[lane + 32], o1);
        }
        float* op = g_attn + (size_t)(b * CTT + CWN + c * 64 + lf) * CE + h * 64;
        op[lane]      = o0;
        op[lane + 32] = o1;
    }
}

// ---------------------------------------------------------------------------
extern "C" void kernel_launch(void* const* d_in, const int* in_sizes, int n_in,
                              void* d_out, int out_size)
{
    const float *x = nullptr, *wm = nullptr, *Wq = nullptr, *bq = nullptr,
                *Wo = nullptr, *bo = nullptr;
    for (int i = 0; i < n_in; i++) {
        switch (in_sizes[i]) {
            case 4259840: x  = (const float*)d_in[i]; break;  // (4,4160,256)
            case 1048576: wm = (const float*)d_in[i]; break;  // (4,64,4096)
            case  196608: Wq = (const float*)d_in[i]; break;  // (256,768)
            case     768: bq = (const float*)d_in[i]; break;
            case   65536: Wo = (const float*)d_in[i]; break;  // (256,256)
            case     256: bo = (const float*)d_in[i]; break;
            default: break;
        }
    }

    cudaFuncSetAttribute(k_qkv, cudaFuncAttributeMaxDynamicSharedMemorySize,
                         GEMM_SMEM_BYTES);
    cudaFuncSetAttribute(k_out, cudaFuncAttributeMaxDynamicSharedMemorySize,
                         GEMM_SMEM_BYTES);
    cudaFuncSetAttribute(k_attn, cudaFuncAttributeMaxDynamicSharedMemorySize,
                         ATTN_WORDS * 4);

    // 1) qkv = x @ W_qkv + b_qkv   (tf32 tensor cores, cp.async 3-stage)
    k_qkv<<<dim3(768 / 128, (CB * CTT) / 128), 256, GEMM_SMEM_BYTES>>>(x, Wq, bq);
    // 2) expa = wm^T @ x_words  (+ z==4 slice: word-token passthrough)
    k_expa<<<dim3(CE / 64, CF / 64, CB + 1), 256>>>(wm, x);
    // 3) shuffle-free SIMT attention, 4 blocks/SM
    k_attn<<<dim3(CF / 64, CB * CH), 256, ATTN_WORDS * 4>>>();
    // 4) out = attn @ W_out + b_out (tf32 tensor cores, cp.async 3-stage)
    k_out<<<dim3(256 / 128, (CB * CTT) / 128), 256, GEMM_SMEM_BYTES>>>(Wo, bo, (float*)d_out);
}

// round 14
// speedup vs baseline: 1.7567x; 1.0440x over previous
#include <cuda_runtime.h>
#include <stdint.h>
#include <math.h>

// Problem constants
#define CB   4          // batch
#define CTT  4160       // total tokens = W + F
#define CF   4096       // frames
#define CWN  64         // windows (word tokens)
#define CE   256        // embed dim
#define CH   4          // heads
#define CD   64         // head dim
#define LS   15         // local window
#define HALO 7
#define QSCALE 0.125f   // 64^-0.5 (exact power of two)

// Scratch (device globals: allocation-free)
__device__ float g_qkv [CB * CTT * 768];   // (b,t, [Q|K|V] x 256)
__device__ float g_expa[CB * CF  * CE];    // (b,f,e)
__device__ float g_attn[CB * CTT * CE];    // (b,t,e) pre-output-projection

__device__ __forceinline__ unsigned int f2tf(float x) {
    unsigned int r;
    asm("cvt.rna.tf32.f32 %0, %1;" : "=r"(r) : "f"(x));
    return r;
}

__device__ __forceinline__ void mma_tf32(float* d, const unsigned int* a,
                                         const unsigned int* b) {
    asm volatile(
        "mma.sync.aligned.m16n8k8.row.col.f32.tf32.tf32.f32 "
        "{%0,%1,%2,%3}, {%4,%5,%6,%7}, {%8,%9}, {%0,%1,%2,%3};"
        : "+f"(d[0]), "+f"(d[1]), "+f"(d[2]), "+f"(d[3])
        : "r"(a[0]), "r"(a[1]), "r"(a[2]), "r"(a[3]), "r"(b[0]), "r"(b[1]));
}

__device__ __forceinline__ void cp16(void* smem, const void* gmem) {
    unsigned int saddr = (unsigned int)__cvta_generic_to_shared(smem);
    asm volatile("cp.async.cg.shared.global [%0], [%1], 16;"
                 :: "r"(saddr), "l"(gmem));
}
// cp.async with src-size: bytes beyond src_sz are zero-filled (src_sz=0 -> all zeros)
__device__ __forceinline__ void cp16z(void* smem, const void* gmem, int src_sz) {
    unsigned int saddr = (unsigned int)__cvta_generic_to_shared(smem);
    asm volatile("cp.async.cg.shared.global [%0], [%1], 16, %2;"
                 :: "r"(saddr), "l"(gmem), "r"(src_sz));
}
#define CP_COMMIT() asm volatile("cp.async.commit_group;" ::: "memory")
#define CP_WAIT(n)  asm volatile("cp.async.wait_group %0;" :: "n"(n) : "memory")

// ---------------------------------------------------------------------------
// TF32 tensor-core GEMM, 2-stage double-buffered cp.async pipeline.
// C[M x N] = A[M x K] @ B[K x N] + bias.  BM=128, BN=128, BK=32, 256 thr.
// 71.7 KB smem -> 2 blocks/SM (regs capped at 128 via launch bounds).
// ---------------------------------------------------------------------------
#define AS_STAGE (128 * 36)
#define BS_STAGE (32 * 136)
#define GEMM_SMEM_BYTES ((2 * AS_STAGE + 2 * BS_STAGE) * 4)

template <int N, int K>
__device__ __forceinline__ void tf32_gemm_core(const float* __restrict__ A,
                                               const float* __restrict__ B,
                                               const float* __restrict__ bias,
                                               float* __restrict__ C)
{
    constexpr int BK = 32;
    constexpr int ITERS = K / BK;

    extern __shared__ float gsm[];
    float* Asm = gsm;                 // [2][128][36]
    float* Bsm = gsm + 2 * AS_STAGE;  // [2][32][136]

    const int tid  = threadIdx.x;
    const int warp = tid >> 5, lane = tid & 31;
    const int wm_  = warp >> 2;
    const int wn_  = warp & 3;
    const int gid  = lane >> 2;
    const int tg   = lane & 3;
    const int m0   = blockIdx.y * 128;
    const int n0   = blockIdx.x * 128;

    auto issue_stage = [&](int s, int k0) {
        float* as = Asm + s * AS_STAGE;
        float* bs = Bsm + s * BS_STAGE;
        #pragma unroll
        for (int p = 0; p < 4; p++) {
            int id  = tid + p * 256;
            int row = id >> 3;
            int kc  = (id & 7) * 4;
            cp16(&as[row * 36 + kc], A + (size_t)(m0 + row) * K + k0 + kc);
        }
        #pragma unroll
        for (int p = 0; p < 4; p++) {
            int id   = tid + p * 256;
            int krow = id >> 5;
            int nc   = (id & 31) * 4;
            cp16(&bs[krow * 136 + nc], B + (size_t)(k0 + krow) * N + n0 + nc);
        }
        CP_COMMIT();
    };

    float acc[4][4][4] = {};

    issue_stage(0, 0);

    for (int it = 0; it < ITERS; it++) {
        if (it + 1 < ITERS) {
            issue_stage((it + 1) & 1, (it + 1) * BK);
            CP_WAIT(1);           // stage `it` complete; `it+1` still in flight
        } else {
            CP_WAIT(0);
        }
        __syncthreads();

        const int s = it & 1;
        const float* as = Asm + s * AS_STAGE;
        const float* bs = Bsm + s * BS_STAGE;

        #pragma unroll
        for (int ks = 0; ks < 4; ks++) {
            const int kb = ks * 8;
            unsigned int af[4][4], bf[4][2];
            #pragma unroll
            for (int mi = 0; mi < 4; mi++) {
                int mr = wm_ * 64 + mi * 16 + gid;
                af[mi][0] = f2tf(as[ mr      * 36 + kb + tg    ]);
                af[mi][1] = f2tf(as[(mr + 8) * 36 + kb + tg    ]);
                af[mi][2] = f2tf(as[ mr      * 36 + kb + tg + 4]);
                af[mi][3] = f2tf(as[(mr + 8) * 36 + kb + tg + 4]);
            }
            #pragma unroll
            for (int ni = 0; ni < 4; ni++) {
                int nc = wn_ * 32 + ni * 8 + gid;
                bf[ni][0] = f2tf(bs[(kb + tg    ) * 136 + nc]);
                bf[ni][1] = f2tf(bs[(kb + tg + 4) * 136 + nc]);
            }
            #pragma unroll
            for (int mi = 0; mi < 4; mi++)
                #pragma unroll
                for (int ni = 0; ni < 4; ni++)
                    mma_tf32(acc[mi][ni], af[mi], bf[ni]);
        }
        __syncthreads();   // protect stage buffers before next iteration's issue
    }

    #pragma unroll
    for (int ni = 0; ni < 4; ni++) {
        int c0 = n0 + wn_ * 32 + ni * 8 + tg * 2;
        float b0v = bias[c0], b1v = bias[c0 + 1];
        #pragma unroll
        for (int mi = 0; mi < 4; mi++) {
            int r0 = m0 + wm_ * 64 + mi * 16 + gid;
            float2 o0 = { acc[mi][ni][0] + b0v, acc[mi][ni][1] + b1v };
            float2 o1 = { acc[mi][ni][2] + b0v, acc[mi][ni][3] + b1v };
            *(float2*)(C + (size_t)r0 * N + c0)       = o0;
            *(float2*)(C + (size_t)(r0 + 8) * N + c0) = o1;
        }
    }
}

__global__ __launch_bounds__(256, 2)
void k_qkv(const float* __restrict__ x, const float* __restrict__ Wq,
           const float* __restrict__ bq)
{
    tf32_gemm_core<768, 256>(x, Wq, bq, g_qkv);
}

__global__ __launch_bounds__(256, 2)
void k_out(const float* __restrict__ Wo, const float* __restrict__ bo,
           float* __restrict__ out)
{
    tf32_gemm_core<256, 256>(g_attn, Wo, bo, out);
}

// ---------------------------------------------------------------------------
// expa[b,f,e] = sum_w wm[b,w,f] * x[b,w,e]   (K = 64 windows, fp32 exact)
// gridDim.z == 5: the z==4 slice does the word-token passthrough copy.
// ---------------------------------------------------------------------------
__global__ __launch_bounds__(256)
void k_expa(const float* __restrict__ wm, const float* __restrict__ x)
{
    if (blockIdx.z == 4) {
        // word-token rows pass through: g_attn[b, t<64, :] = x[b, t<64, :]
        int i = ((blockIdx.y * 4 + blockIdx.x) * 256) + threadIdx.x; // 0..65535
        int b = i >> 14;
        int r = i & 16383;
        g_attn[(size_t)b * CTT * CE + r] = x[(size_t)b * CTT * CE + r];
        return;
    }

    __shared__ float As[64][64];  // [w][f]
    __shared__ float Bs[64][64];  // [w][e]

    const int b  = blockIdx.z;
    const int f0 = blockIdx.y * 64;
    const int e0 = blockIdx.x * 64;
    const int tid = threadIdx.x;

    for (int i = tid; i < 64 * 16; i += 256) {
        int w  = i >> 4;
        int c4 = (i & 15) * 4;
        *(float4*)&As[w][c4] =
            *(const float4*)(wm + (size_t)(b * CWN + w) * CF + f0 + c4);
        *(float4*)&Bs[w][c4] =
            *(const float4*)(x + (size_t)(b * CTT + w) * CE + e0 + c4);
    }
    __syncthreads();

    const int tx = tid & 15, ty = tid >> 4;
    float acc[4][4] = {};
    #pragma unroll 8
    for (int w = 0; w < 64; w++) {
        float ra[4], rb[4];
        *(float4*)ra = *(const float4*)&As[w][ty * 4];
        *(float4*)rb = *(const float4*)&Bs[w][tx * 4];
        #pragma unroll
        for (int i = 0; i < 4; i++)
            #pragma unroll
            for (int j = 0; j < 4; j++)
                acc[i][j] = fmaf(ra[i], rb[j], acc[i][j]);
    }

    #pragma unroll
    for (int i = 0; i < 4; i++) {
        float4 o = { acc[i][0], acc[i][1], acc[i][2], acc[i][3] };
        *(float4*)(g_expa + (size_t)(b * CF + f0 + ty * 4 + i) * CE + e0 + tx * 4) = o;
    }
}

// ---------------------------------------------------------------------------
// Attention v4 (unchanged from R11): shuffle-free scores, Q via gmem broadcast,
// 46.2 KB smem, 4 blocks/SM.
// ---------------------------------------------------------------------------
#define KST 68
#define AROWS 78
#define AOFF_K 0
#define AOFF_V (AROWS * KST)                 // 5304
#define AOFF_S (2 * AROWS * KST)             // 10608
#define AOFF_S0 (AOFF_S + 64 * 17)           // 11696
#define AOFF_W0 (AOFF_S0 + 64)               // 11760
#define ATTN_WORDS (AOFF_W0 + 64)            // 11824 -> 47296 B

__global__ __launch_bounds__(256, 4)
void k_attn()
{
    extern __shared__ float sa[];
    float* sK = sa + AOFF_K;
    float* sV = sa + AOFF_V;
    float* sS = sa + AOFF_S;
    float* s0 = sa + AOFF_S0;
    float* w0 = sa + AOFF_W0;

    const int n = blockIdx.y, c = blockIdx.x;
    const int b = n >> 2, h = n & 3;
    const int tid = threadIdx.x;
    const int warp = tid >> 5, lane = tid & 31;

    const float* Qg = g_qkv + (size_t)(b * CTT + CWN + c * 64) * 768 + h * 64;

    // ---- stage K/V halo (zero-filled OOB) via cp.async ----
    for (int i = tid; i < AROWS * 16; i += 256) {
        int row = i >> 4, c4 = (i & 15) * 4;
        int gf  = c * 64 - HALO + row;
        int ok  = (gf >= 0 && gf < CF);
        int gfc = ok ? gf : 0;
        const float* base = g_qkv + (size_t)(b * CTT + CWN + gfc) * 768 + h * 64 + c4;
        cp16z(&sK[row * KST + c4], base + 256, ok ? 16 : 0);
        cp16z(&sV[row * KST + c4], base + 512, ok ? 16 : 0);
    }
    CP_COMMIT();

    // ---- word-token scores from gmem Q (overlaps with K/V arrival) ----
    #pragma unroll
    for (int fi = 0; fi < 8; fi++) {
        int lf = warp * 8 + fi;
        const float* qp = Qg + (size_t)lf * 768;
        const float* ep = g_expa + (size_t)(b * CF + c * 64 + lf) * CE + h * 64;
        float p = qp[lane] * ep[lane] + qp[lane + 32] * ep[lane + 32];
        #pragma unroll
        for (int off = 16; off; off >>= 1)
            p += __shfl_xor_sync(0xffffffffu, p, off);
        if (lane == 0) s0[lf] = p * QSCALE;
    }

    CP_WAIT(0);
    __syncthreads();

    // ---- local scores: lane-per-score, Q broadcast from gmem, K from smem ----
    {
        const int j    = lane & 15;
        const int half = lane >> 4;
        #pragma unroll
        for (int pass = 0; pass < 4; pass++) {
            int f = pass * 16 + warp * 2 + half;
            if (j < LS) {
                const float* qr = Qg + (size_t)f * 768;
                const float* kr = sK + (f + j) * KST;
                float a0 = 0.f, a1 = 0.f;
                #pragma unroll
                for (int e = 0; e < 64; e += 4) {
                    float4 qv = *(const float4*)(qr + e);
                    float4 kv = *(const float4*)(kr + e);
                    a0 = fmaf(qv.x, kv.x, a0);
                    a1 = fmaf(qv.y, kv.y, a1);
                    a0 = fmaf(qv.z, kv.z, a0);
                    a1 = fmaf(qv.w, kv.w, a1);
                }
                sS[f * 17 + j] = (a0 + a1) * QSCALE;
            }
        }
    }
    __syncthreads();

    // ---- chunk softmax (warp 0) + local softmax (tid<64) ----
    if (warp == 0) {
        float v0 = s0[lane], v1 = s0[lane + 32];
        float M = fmaxf(v0, v1);
        #pragma unroll
        for (int off = 16; off; off >>= 1)
            M = fmaxf(M, __shfl_xor_sync(0xffffffffu, M, off));
        float S = expf(v0 - M) + expf(v1 - M);
        #pragma unroll
        for (int off = 16; off; off >>= 1)
            S += __shfl_xor_sync(0xffffffffu, S, off);
        float Sinv = 1.f / S;
        w0[lane]      = expf(v0 - M) * Sinv;
        w0[lane + 32] = expf(v1 - M) * Sinv;
    }
    if (tid < 64) {
        float p[LS];
        #pragma unroll
        for (int j = 0; j < LS; j++) p[j] = sS[tid * 17 + j];
        float mx = p[0];
        #pragma unroll
        for (int j = 1; j < LS; j++) mx = fmaxf(mx, p[j]);
        float s = 0.f;
        #pragma unroll
        for (int j = 0; j < LS; j++) { p[j] = expf(p[j] - mx); s += p[j]; }
        float inv = 1.f / s;
        #pragma unroll
        for (int j = 0; j < LS; j++) sS[tid * 17 + j] = p[j] * inv;
    }
    __syncthreads();

    // ---- output: o = w0*expa + sum_j w_j * V ----
    #pragma unroll
    for (int fi = 0; fi < 8; fi++) {
        int lf = warp * 8 + fi;
        const float* ep = g_expa + (size_t)(b * CF + c * 64 + lf) * CE + h * 64;
        float wv = w0[lf];
        float o0 = wv * ep[lane];
        float o1 = wv * ep[lane + 32];
        #pragma unroll
        for (int j = 0; j < LS; j++) {
            float wj = sS[lf * 17 + j];
            const float* vr = sV + (lf + j) * KST;
            o0 = fmaf(wj, vr[lane],      o0);
            o1 = fmaf(wj, vr[lane + 32], o1);
        }
        float* op = g_attn + (size_t)(b * CTT + CWN + c * 64 + lf) * CE + h * 64;
        op[lane]      = o0;
        op[lane + 32] = o1;
    }
}

// ---------------------------------------------------------------------------
extern "C" void kernel_launch(void* const* d_in, const int* in_sizes, int n_in,
                              void* d_out, int out_size)
{
    const float *x = nullptr, *wm = nullptr, *Wq = nullptr, *bq = nullptr,
                *Wo = nullptr, *bo = nullptr;
    for (int i = 0; i < n_in; i++) {
        switch (in_sizes[i]) {
            case 4259840: x  = (const float*)d_in[i]; break;  // (4,4160,256)
            case 1048576: wm = (const float*)d_in[i]; break;  // (4,64,4096)
            case  196608: Wq = (const float*)d_in[i]; break;  // (256,768)
            case     768: bq = (const float*)d_in[i]; break;
            case   65536: Wo = (const float*)d_in[i]; break;  // (256,256)
            case     256: bo = (const float*)d_in[i]; break;
            default: break;
        }
    }

    cudaFuncSetAttribute(k_qkv, cudaFuncAttributeMaxDynamicSharedMemorySize,
                         GEMM_SMEM_BYTES);
    cudaFuncSetAttribute(k_out, cudaFuncAttributeMaxDynamicSharedMemorySize,
                         GEMM_SMEM_BYTES);
    cudaFuncSetAttribute(k_attn, cudaFuncAttributeMaxDynamicSharedMemorySize,
                         ATTN_WORDS * 4);

    // 1) qkv = x @ W_qkv + b_qkv   (tf32 tensor cores, 2-stage double buffer)
    k_qkv<<<dim3(768 / 128, (CB * CTT) / 128), 256, GEMM_SMEM_BYTES>>>(x, Wq, bq);
    // 2) expa = wm^T @ x_words  (+ z==4 slice: word-token passthrough)
    k_expa<<<dim3(CE / 64, CF / 64, CB + 1), 256>>>(wm, x);
    // 3) shuffle-free SIMT attention, 4 blocks/SM
    k_attn<<<dim3(CF / 64, CB * CH), 256, ATTN_WORDS * 4>>>();
    // 4) out = attn @ W_out + b_out (tf32 tensor cores, 2-stage double buffer)
    k_out<<<dim3(256 / 128, (CB * CTT) / 128), 256, GEMM_SMEM_BYTES>>>(Wo, bo, (float*)d_out);
}